// round 1
// baseline (speedup 1.0000x reference)
#include <cuda_runtime.h>

// Problem constants
#define BB  32
#define LL  128
#define HH  8
#define EE  64
#define PP  16
#define GG  2          // BB / PP
#define WIN 2048

// Group-mean series accumulator: [G, H, L, L] = 2*8*128*128 floats = 4 MB.
// Static __device__ global (allocation-free scratch per harness rules).
__device__ float g_acc[GG * HH * LL * LL];

// ---------------------------------------------------------------------------
// Kernel 0: zero the accumulator (must run before attn_kernel's atomics).
// ---------------------------------------------------------------------------
__global__ void zero_acc_kernel() {
    int i = blockIdx.x * 256 + threadIdx.x;
    g_acc[i] = 0.0f;
}

// ---------------------------------------------------------------------------
// Kernel 1: per-(b,h) attention. One CTA per (b,h) pair -> 256 CTAs.
//   smem: sQ[128][64] | sK[128][64] | sV[128][64] | sP[128][128]  = 160 KB
//   Phase 1: scores = Q K^T        (K column register-resident per thread)
//   Phase 2: softmax (warp/row) + atomicAdd of p/16 into g_acc (group mean)
//   Phase 3: out V = P @ Vin       (V scalars hoisted, 32 row-accs in regs)
// ---------------------------------------------------------------------------
__global__ void __launch_bounds__(256, 1) attn_kernel(
    const float* __restrict__ Q, const float* __restrict__ K,
    const float* __restrict__ V, float* __restrict__ outV)
{
    extern __shared__ float sm[];
    float* sQ = sm;
    float* sK = sm + LL * EE;
    float* sV = sm + 2 * LL * EE;
    float* sP = sm + 3 * LL * EE;

    const int b = blockIdx.x >> 3;
    const int h = blockIdx.x & 7;
    const int t = threadIdx.x;

    // Global base of element (b, 0, h, 0); row l is at +l*H*E floats.
    const size_t base = ((size_t)b * LL * HH + h) * EE;
    const float4* q4 = (const float4*)(Q + base);
    const float4* k4 = (const float4*)(K + base);
    const float4* v4 = (const float4*)(V + base);
    // Row stride in float4 units: H*E/4 = 128. E/4 = 16 float4 per row.
    for (int i = t; i < LL * EE / 4; i += 256) {
        int row = i >> 4;
        int c4  = i & 15;
        int g   = row * 128 + c4;
        ((float4*)sQ)[i] = q4[g];
        ((float4*)sK)[i] = k4[g];
        ((float4*)sV)[i] = v4[g];
    }
    __syncthreads();

    // -------- Phase 1: scores[r][c] = dot64(Q[r], K[c]) --------
    {
        const int c  = t & 127;          // this thread's key column
        const int r0 = t >> 7;           // 0: even rows, 1: odd rows
        float4 kc[16];
        #pragma unroll
        for (int i = 0; i < 16; i++)
            kc[i] = ((const float4*)(sK + c * EE))[i];

        for (int rr = 0; rr < 64; ++rr) {
            const int r = r0 + 2 * rr;
            const float4* qr = (const float4*)(sQ + r * EE);  // broadcast LDS
            float acc = 0.0f;
            #pragma unroll
            for (int i = 0; i < 16; i++) {
                float4 qv = qr[i];
                acc = fmaf(qv.x, kc[i].x, acc);
                acc = fmaf(qv.y, kc[i].y, acc);
                acc = fmaf(qv.z, kc[i].z, acc);
                acc = fmaf(qv.w, kc[i].w, acc);
            }
            sP[r * LL + c] = acc;
        }
    }
    __syncthreads();

    // -------- Phase 2: row softmax + group-mean accumulation --------
    {
        const int warp = t >> 5, lane = t & 31;
        const int g = b >> 4;            // batch group of 16
        float* accb = g_acc + ((size_t)(g * HH + h) * LL) * LL;
        const float scale = 0.125f;      // 1/sqrt(64)
        const float gsc   = 1.0f / 16.0f;

        for (int r = warp; r < LL; r += 8) {
            float* row = sP + r * LL;
            float v0 = row[lane], v1 = row[lane + 32];
            float v2 = row[lane + 64], v3 = row[lane + 96];
            float m = fmaxf(fmaxf(v0, v1), fmaxf(v2, v3));
            #pragma unroll
            for (int o = 16; o; o >>= 1)
                m = fmaxf(m, __shfl_xor_sync(0xffffffffu, m, o));
            float e0 = __expf(scale * (v0 - m));
            float e1 = __expf(scale * (v1 - m));
            float e2 = __expf(scale * (v2 - m));
            float e3 = __expf(scale * (v3 - m));
            float s = e0 + e1 + e2 + e3;
            #pragma unroll
            for (int o = 16; o; o >>= 1)
                s += __shfl_xor_sync(0xffffffffu, s, o);
            float inv = 1.0f / s;
            e0 *= inv; e1 *= inv; e2 *= inv; e3 *= inv;
            row[lane]      = e0;
            row[lane + 32] = e1;
            row[lane + 64] = e2;
            row[lane + 96] = e3;
            float* ab = accb + (size_t)r * LL + lane;
            atomicAdd(ab,      e0 * gsc);
            atomicAdd(ab + 32, e1 * gsc);
            atomicAdd(ab + 64, e2 * gsc);
            atomicAdd(ab + 96, e3 * gsc);
        }
    }
    __syncthreads();

    // -------- Phase 3: outV[r][d] = sum_s P[r][s] * Vin[s][d] --------
    {
        const int d  = t & 63;
        const int rg = t >> 6;           // 4 row-groups of 32 rows
        float acc[32];
        #pragma unroll
        for (int j = 0; j < 32; j++) acc[j] = 0.0f;

        const float* pbase = sP + (rg * 32) * LL;
        for (int s = 0; s < LL; s += 4) {
            float w0 = sV[(s + 0) * EE + d];
            float w1 = sV[(s + 1) * EE + d];
            float w2 = sV[(s + 2) * EE + d];
            float w3 = sV[(s + 3) * EE + d];
            #pragma unroll
            for (int j = 0; j < 32; j++) {
                float4 p4 = *(const float4*)(pbase + j * LL + s);  // broadcast
                acc[j] = fmaf(p4.x, w0,
                          fmaf(p4.y, w1,
                           fmaf(p4.z, w2,
                            fmaf(p4.w, w3, acc[j]))));
            }
        }
        float* ov = outV + ((size_t)(b * LL) * HH + h) * EE + d;
        #pragma unroll
        for (int j = 0; j < 32; j++) {
            int r = rg * 32 + j;
            ov[(size_t)r * HH * EE] = acc[j];
        }
    }
}

// ---------------------------------------------------------------------------
// Kernel 2: series output. One CTA per output row (g,h,i): 2*8*2048 = 32768
// rows of 2048 floats. out[g,h,i,j] = g_acc[g,h, i%128, j%128] (scale already
// folded into the atomicAdd). Source rows live in L2 (4 MB); pure write BW.
// ---------------------------------------------------------------------------
__global__ void __launch_bounds__(256) tile_kernel(float* __restrict__ outS) {
    const int rowid = blockIdx.x;             // [0, 32768)
    const int i  = rowid & (WIN - 1);
    const int gh = rowid >> 11;               // WIN = 2048
    const float* src = g_acc + ((size_t)gh * LL + (i & (LL - 1))) * LL;
    const int t = threadIdx.x;

    float4 v = *(const float4*)(src + ((4 * t) & (LL - 1)));
    float4* d4 = (float4*)(outS + (size_t)rowid * WIN);
    d4[t]       = v;   // j in [0,1024): (4t) % 128
    d4[t + 256] = v;   // j in [1024,2048): same source (1024 % 128 == 0)
}

// ---------------------------------------------------------------------------
// Launch: zero -> attention(+mean accumulate) -> tiled series write.
// All on the capture stream, no syncs, no allocs.
// ---------------------------------------------------------------------------
extern "C" void kernel_launch(void* const* d_in, const int* in_sizes, int n_in,
                              void* d_out, int out_size) {
    (void)in_sizes; (void)n_in; (void)out_size;
    const float* Q = (const float*)d_in[0];
    const float* K = (const float*)d_in[1];
    const float* V = (const float*)d_in[2];
    // d_in[3] is patch_index (always 0 -> the p=16 tile/mean branch).

    float* outV = (float*)d_out;                       // [32,128,8,64]
    float* outS = outV + (size_t)BB * LL * HH * EE;    // [2,8,2048,2048]

    const int smem = (3 * LL * EE + LL * LL) * (int)sizeof(float);  // 160 KB
    cudaFuncSetAttribute(attn_kernel,
                         cudaFuncAttributeMaxDynamicSharedMemorySize, smem);

    zero_acc_kernel<<<GG * HH * LL * LL / 256, 256>>>();
    attn_kernel<<<BB * HH, 256, smem>>>(Q, K, V, outV);
    tile_kernel<<<GG * HH * WIN, 256>>>(outS);
}